// round 13
// baseline (speedup 1.0000x reference)
#include <cuda_runtime.h>
#include <cuda_fp16.h>
#include <cstdint>
#include <math.h>

// ---------------------------------------------------------------------------
// InteractionLayer via fp16 mma.sync m16n8k16 + 4-stage cp.async + ldmatrix
// (arch-portable PTX; harness targets plain sm_103 — no 'a' features).
// R13: exact R10 GEMM config (best known: BK=32, NSTAGE=4, no split-K).
// Schedule-only changes: pass-through memcpy on its own stream (joined at
// end), V projection starts right after cvt on stream 2, LN processes 2 rows
// per block. Softmax fused in GEMM epilogues (exp + partial row sums).
// ---------------------------------------------------------------------------

#define ND 2048
#define NR 2048
#define NB 8
#define DM 512
#define DF 512
#define PSUM_BLKS 8   // scores gridDim.y = ND/256

// scratch (no cudaMalloc allowed)
__device__ __align__(16) __half g_det16[(size_t)ND * NB * DM];
__device__ __align__(16) __half g_rel16[(size_t)NR * NB * DM];
__device__ __align__(16) __half g_wd16[(size_t)DF * DM];
__device__ __align__(16) __half g_wr16[(size_t)DF * DM];
__device__ __align__(16) __half g_wv16[(size_t)DF * DM];
__device__ __align__(16) __half g_q16[(size_t)NB * ND * DF];
__device__ __align__(16) __half g_k16[(size_t)NB * NR * DF];
__device__ __align__(16) __half g_v16[(size_t)NB * ND * DF];
__device__ __align__(16) __half g_s16[(size_t)NB * NR * ND];    // exp weights
__device__ __align__(16) __half g_add16[(size_t)NB * NR * DF];  // rel_add
__device__ __align__(16) float  g_psum[(size_t)NB * PSUM_BLKS * NR];

__device__ __forceinline__ uint32_t smem_u32(const void* p) {
    uint32_t a;
    asm("{ .reg .u64 t; cvta.to.shared.u64 t, %1; cvt.u32.u64 %0, t; }" : "=r"(a) : "l"(p));
    return a;
}
__device__ __forceinline__ void cp16(uint32_t dst, const void* src) {
    asm volatile("cp.async.cg.shared.global [%0], [%1], 16;" :: "r"(dst), "l"(src) : "memory");
}
#define CP_COMMIT() asm volatile("cp.async.commit_group;" ::: "memory")

__device__ __forceinline__ void ldsm4(uint32_t* r, uint32_t a) {
    asm volatile("ldmatrix.sync.aligned.m8n8.x4.shared.b16 {%0,%1,%2,%3}, [%4];"
                 : "=r"(r[0]), "=r"(r[1]), "=r"(r[2]), "=r"(r[3]) : "r"(a));
}
__device__ __forceinline__ void ldsm4t(uint32_t* r, uint32_t a) {
    asm volatile("ldmatrix.sync.aligned.m8n8.x4.trans.shared.b16 {%0,%1,%2,%3}, [%4];"
                 : "=r"(r[0]), "=r"(r[1]), "=r"(r[2]), "=r"(r[3]) : "r"(a));
}
__device__ __forceinline__ float fex2(float x) {
    float r;
    asm("ex2.approx.f32 %0, %1;" : "=f"(r) : "f"(x));
    return r;
}

// smem halves per buffer (30720 B): As 128x40 (10240 B), Bs 20480 B
// (NT: 256x40; NN: 32x264). FOUR buffers: 122880 B.
#define AS_STRIDE 40
#define BNT_STRIDE 40
#define BNN_STRIDE 264
#define BUF_BYTES 30720
#define NSTAGE 4
#define SMEM_BYTES (NSTAGE * BUF_BYTES)

// ---------------------------------------------------------------------------
// Core GEMM body. 256 threads, 8 warps (2x4), warp tile 64x64, CTA 128x256.
// BNN=false (NT): C[m,n] = sum_k A[m*rsA+k] * B[n*rsB+k]
// BNN=true  (NN): C[m,n] = sum_k A[m*rsA+k] * B[k*rsB+n]
// EPI: 0 = bias add; 1 = exp(acc*escale) + partial row sums into aux;
//      2 = multiply by 1/(sum of PSUM_BLKS partials from aux).
// ---------------------------------------------------------------------------
template <bool BNN, int EPI, typename OutT>
__device__ __forceinline__ void gemm_body(
    const __half* __restrict__ A, const __half* __restrict__ B, OutT* __restrict__ C,
    const float* __restrict__ bias, float* __restrict__ aux, float escale,
    int K, long rsA, long rsB, long rsC)
{
    extern __shared__ __align__(16) char dyn[];
    const uint32_t sb = smem_u32(dyn);

    const int tid = threadIdx.x;
    const int wid = tid >> 5;
    const int lane = tid & 31;
    const int g = lane >> 2;
    const int c = lane & 3;
    const int t8 = lane >> 3;
    const int lr = lane & 7;
    const int wm = (wid >> 2) * 64;
    const int wn = (wid & 3) * 64;

    const long rowBase = (long)blockIdx.x * 128;
    const long colBase = (long)blockIdx.y * 256;

    float acc[4][8][4];
    #pragma unroll
    for (int mt = 0; mt < 4; mt++)
        #pragma unroll
        for (int nt = 0; nt < 8; nt++)
            #pragma unroll
            for (int r = 0; r < 4; r++) acc[mt][nt][r] = 0.f;

    const int NS = K / 32;

    auto issue = [&](int s) {
        const int buf = s % NSTAGE;
        const long k0 = (long)s * 32;
        const uint32_t ab = sb + buf * BUF_BYTES;
        const uint32_t bb = ab + 10240;
        #pragma unroll
        for (int i = 0; i < 2; i++) {
            const int idx = i * 256 + tid;
            const int row = idx >> 2, ch = idx & 3;
            cp16(ab + (row * AS_STRIDE + ch * 8) * 2,
                 &A[(rowBase + row) * rsA + k0 + ch * 8]);
        }
        if (BNN) {
            #pragma unroll
            for (int i = 0; i < 4; i++) {
                const int idx = i * 256 + tid;
                const int kr = idx >> 5, ch = idx & 31;
                cp16(bb + (kr * BNN_STRIDE + ch * 8) * 2,
                     &B[(k0 + kr) * rsB + colBase + ch * 8]);
            }
        } else {
            #pragma unroll
            for (int i = 0; i < 4; i++) {
                const int idx = i * 256 + tid;
                const int row = idx >> 2, ch = idx & 3;
                cp16(bb + (row * BNT_STRIDE + ch * 8) * 2,
                     &B[(colBase + row) * rsB + k0 + ch * 8]);
            }
        }
        CP_COMMIT();
    };

    issue(0);
    if (NS > 1) issue(1);
    if (NS > 2) issue(2);

    for (int s = 0; s < NS; s++) {
        if (s + 3 <= NS)
            asm volatile("cp.async.wait_group 2;" ::: "memory");
        else if (s + 2 == NS)
            asm volatile("cp.async.wait_group 1;" ::: "memory");
        else
            asm volatile("cp.async.wait_group 0;" ::: "memory");
        __syncthreads();

        const uint32_t ab = sb + (s % NSTAGE) * BUF_BYTES;
        const uint32_t bb = ab + 10240;

        #pragma unroll
        for (int kk = 0; kk < 2; kk++) {
            const int k0h = kk * 16;
            uint32_t a[4][4];
            #pragma unroll
            for (int mt = 0; mt < 4; mt++)
                ldsm4(a[mt], ab + ((wm + mt * 16 + (t8 & 1) * 8 + lr) * AS_STRIDE
                                   + k0h + (t8 >> 1) * 8) * 2);
            uint32_t b[4][4];
            #pragma unroll
            for (int np = 0; np < 4; np++) {
                if (BNN)
                    ldsm4t(b[np], bb + ((k0h + (t8 & 1) * 8 + lr) * BNN_STRIDE
                                        + wn + np * 16 + (t8 >> 1) * 8) * 2);
                else
                    ldsm4(b[np], bb + ((wn + np * 16 + (t8 >> 1) * 8 + lr) * BNT_STRIDE
                                       + k0h + (t8 & 1) * 8) * 2);
            }
            #pragma unroll
            for (int mt = 0; mt < 4; mt++)
                #pragma unroll
                for (int nt = 0; nt < 8; nt++)
                    asm volatile(
                        "mma.sync.aligned.m16n8k16.row.col.f32.f16.f16.f32 "
                        "{%0,%1,%2,%3}, {%4,%5,%6,%7}, {%8,%9}, {%0,%1,%2,%3};"
                        : "+f"(acc[mt][nt][0]), "+f"(acc[mt][nt][1]),
                          "+f"(acc[mt][nt][2]), "+f"(acc[mt][nt][3])
                        : "r"(a[mt][0]), "r"(a[mt][1]), "r"(a[mt][2]), "r"(a[mt][3]),
                          "r"(b[nt >> 1][(nt & 1) * 2]), "r"(b[nt >> 1][(nt & 1) * 2 + 1]));
        }
        if (s + 3 < NS) issue(s + 3);
    }

    const long nRowsTot = (long)gridDim.x * 128;

    // ---- epilogue
    float rsum[4][2];
    #pragma unroll
    for (int mt = 0; mt < 4; mt++) { rsum[mt][0] = 0.f; rsum[mt][1] = 0.f; }

    #pragma unroll
    for (int mt = 0; mt < 4; mt++) {
        const long row0 = rowBase + wm + mt * 16 + g;
        float sc0 = 1.f, sc1 = 1.f;
        if (EPI == 2) {
            float s0 = 0.f, s1 = 0.f;
            #pragma unroll
            for (int k = 0; k < PSUM_BLKS; k++) {
                s0 += aux[(long)k * nRowsTot + row0];
                s1 += aux[(long)k * nRowsTot + row0 + 8];
            }
            sc0 = 1.f / s0;
            sc1 = 1.f / s1;
        }
        #pragma unroll
        for (int nt = 0; nt < 8; nt++) {
            const long col = colBase + wn + nt * 8 + 2 * c;
            float x0 = acc[mt][nt][0], x1 = acc[mt][nt][1];
            float x2 = acc[mt][nt][2], x3 = acc[mt][nt][3];
            if (EPI == 0) {
                float bx = 0.f, by = 0.f;
                if (bias) { bx = bias[col]; by = bias[col + 1]; }
                x0 += bx; x1 += by; x2 += bx; x3 += by;
            } else if (EPI == 1) {
                x0 = fex2(x0 * escale); x1 = fex2(x1 * escale);
                x2 = fex2(x2 * escale); x3 = fex2(x3 * escale);
                rsum[mt][0] += x0 + x1;
                rsum[mt][1] += x2 + x3;
            } else {
                x0 *= sc0; x1 *= sc0; x2 *= sc1; x3 *= sc1;
            }
            if (sizeof(OutT) == 2) {
                *reinterpret_cast<__half2*>(C + row0 * rsC + col) = __floats2half2_rn(x0, x1);
                *reinterpret_cast<__half2*>(C + (row0 + 8) * rsC + col) = __floats2half2_rn(x2, x3);
            } else {
                *reinterpret_cast<float2*>((float*)C + row0 * rsC + col) = make_float2(x0, x1);
                *reinterpret_cast<float2*>((float*)C + (row0 + 8) * rsC + col) = make_float2(x2, x3);
            }
        }
    }

    if (EPI == 1) {
        float* sred = reinterpret_cast<float*>(dyn);   // [128 rows][4 n-warps]
        __syncthreads();
        #pragma unroll
        for (int mt = 0; mt < 4; mt++) {
            float v0 = rsum[mt][0], v1 = rsum[mt][1];
            v0 += __shfl_xor_sync(0xFFFFFFFFu, v0, 1);
            v0 += __shfl_xor_sync(0xFFFFFFFFu, v0, 2);
            v1 += __shfl_xor_sync(0xFFFFFFFFu, v1, 1);
            v1 += __shfl_xor_sync(0xFFFFFFFFu, v1, 2);
            if (c == 0) {
                const int rl = wm + mt * 16 + g;
                sred[rl * 4 + (wid & 3)] = v0;
                sred[(rl + 8) * 4 + (wid & 3)] = v1;
            }
        }
        __syncthreads();
        if (tid < 128) {
            const float s = sred[tid * 4] + sred[tid * 4 + 1]
                          + sred[tid * 4 + 2] + sred[tid * 4 + 3];
            aux[(long)blockIdx.y * nRowsTot + rowBase + tid] = s;
        }
    }
}

// Generic batched wrapper.
template <bool BNN, int EPI, typename OutT>
__global__ __launch_bounds__(256, 1) void hgemm(
    const __half* __restrict__ A, const __half* __restrict__ B, OutT* __restrict__ C,
    const float* __restrict__ bias, float* __restrict__ aux, long auxStride,
    float escale, int K,
    long rsA, long bsA, long rsB, long bsB, long rsC, long bsC)
{
    const int bz = blockIdx.z;
    gemm_body<BNN, EPI, OutT>(A + (long)bz * bsA, B + (long)bz * bsB,
                              C + (long)bz * bsC, bias,
                              aux ? aux + (long)bz * auxStride : nullptr,
                              escale, K, rsA, rsB, rsC);
}

// Q+K projections in one launch: z = which*NB + b.
__global__ __launch_bounds__(256, 1) void hgemm_projqk(
    const __half* __restrict__ det16, const __half* __restrict__ rel16,
    const __half* __restrict__ wd, const __half* __restrict__ wr,
    const float* __restrict__ bd, const float* __restrict__ br,
    __half* __restrict__ q16, __half* __restrict__ k16)
{
    const int z = blockIdx.z;
    const int which = z >> 3;
    const int b = z & 7;
    const __half* A = which ? rel16 : det16;
    const __half* W = which ? wr : wd;
    const float* bias = which ? br : bd;
    __half* C = which ? k16 : q16;
    gemm_body<false, 0, __half>(A + (long)b * DM, W, C + (long)b * ND * DF,
                                bias, nullptr, 0.f, DM, (long)NB * DM, DM, DF);
}

// ---------------------------------------------------------------------------
// One launch converting all five fp32 tensors to fp16.
// ---------------------------------------------------------------------------
__global__ __launch_bounds__(256) void cvt_all(
    const float* __restrict__ det, const float* __restrict__ rel,
    const float* __restrict__ wd, const float* __restrict__ wr,
    const float* __restrict__ wv,
    __half* __restrict__ det16, __half* __restrict__ rel16,
    __half* __restrict__ wd16, __half* __restrict__ wr16, __half* __restrict__ wv16)
{
    const float* src; __half* dst; long n;
    switch (blockIdx.z) {
        case 0: src = det; dst = det16; n = (long)ND * NB * DM; break;
        case 1: src = rel; dst = rel16; n = (long)NR * NB * DM; break;
        case 2: src = wd;  dst = wd16;  n = (long)DF * DM; break;
        case 3: src = wr;  dst = wr16;  n = (long)DF * DM; break;
        default: src = wv; dst = wv16;  n = (long)DF * DM; break;
    }
    long i = ((long)blockIdx.x * blockDim.x + threadIdx.x) * 4;
    const long stride = (long)gridDim.x * blockDim.x * 4;
    for (; i < n; i += stride) {
        float4 v = *reinterpret_cast<const float4*>(src + i);
        __half2* p = reinterpret_cast<__half2*>(dst + i);
        p[0] = __floats2half2_rn(v.x, v.y);
        p[1] = __floats2half2_rn(v.z, v.w);
    }
}

// ---------------------------------------------------------------------------
// out[r][b][:] = LN(add16[b][r][:] + rel_in[r][b][:]) * gamma + beta
// 256 threads = 2 rows per block (grid 8192).
// ---------------------------------------------------------------------------
__global__ __launch_bounds__(256) void residual_ln(
    const __half* __restrict__ add, const float* __restrict__ rel_in,
    const float* __restrict__ gamma, const float* __restrict__ beta,
    float* __restrict__ out)
{
    const int half = threadIdx.x >> 7;            // which of the 2 rows
    const int tid = threadIdx.x & 127;
    const long idx = (long)blockIdx.x * 2 + half; // b*NR + r
    const long b = idx >> 11;
    const long r = idx & 2047;
    const int f = tid * 4;

    uint2 araw = *reinterpret_cast<const uint2*>(&add[idx * DM + f]);
    const __half2* ah = reinterpret_cast<const __half2*>(&araw);
    float2 a01 = __half22float2(ah[0]);
    float2 a23 = __half22float2(ah[1]);
    const float4 r4 = *reinterpret_cast<const float4*>(&rel_in[(r * NB + b) * DM + f]);
    float x0 = a01.x + r4.x, x1 = a01.y + r4.y, x2 = a23.x + r4.z, x3 = a23.y + r4.w;

    float sum = x0 + x1 + x2 + x3;
    float ssq = x0 * x0 + x1 * x1 + x2 * x2 + x3 * x3;
    #pragma unroll
    for (int o = 16; o > 0; o >>= 1) {
        sum += __shfl_xor_sync(0xFFFFFFFFu, sum, o);
        ssq += __shfl_xor_sync(0xFFFFFFFFu, ssq, o);
    }
    __shared__ float s1[2][4], s2[2][4];
    const int w = tid >> 5;
    if ((tid & 31) == 0) { s1[half][w] = sum; s2[half][w] = ssq; }
    __syncthreads();
    sum = s1[half][0] + s1[half][1] + s1[half][2] + s1[half][3];
    ssq = s2[half][0] + s2[half][1] + s2[half][2] + s2[half][3];

    const float mean = sum * (1.f / DM);
    const float var = ssq * (1.f / DM) - mean * mean;
    const float rstd = rsqrtf(var + 1e-5f);

    const float4 g4 = *reinterpret_cast<const float4*>(&gamma[f]);
    const float4 be4 = *reinterpret_cast<const float4*>(&beta[f]);
    float4 o4;
    o4.x = (x0 - mean) * rstd * g4.x + be4.x;
    o4.y = (x1 - mean) * rstd * g4.y + be4.y;
    o4.z = (x2 - mean) * rstd * g4.z + be4.z;
    o4.w = (x3 - mean) * rstd * g4.w + be4.w;
    *reinterpret_cast<float4*>(&out[(r * NB + b) * DM + f]) = o4;
}

// ---------------------------------------------------------------------------
extern "C" void kernel_launch(void* const* d_in, const int* in_sizes, int n_in,
                              void* d_out, int out_size)
{
    const float* det_in = (const float*)d_in[0];
    const float* rel_in = (const float*)d_in[1];
    const float* W_det  = (const float*)d_in[2];
    const float* b_det  = (const float*)d_in[3];
    const float* W_rel  = (const float*)d_in[4];
    const float* b_rel  = (const float*)d_in[5];
    const float* W_val  = (const float*)d_in[6];
    const float* b_val  = (const float*)d_in[7];
    const float* gamma  = (const float*)d_in[8];
    const float* beta   = (const float*)d_in[9];
    float* out = (float*)d_out;

    __half *det16, *rel16, *wd16, *wr16, *wv16, *q16, *k16, *v16, *s16, *add16;
    float *psum;
    cudaGetSymbolAddress((void**)&det16, g_det16);
    cudaGetSymbolAddress((void**)&rel16, g_rel16);
    cudaGetSymbolAddress((void**)&wd16, g_wd16);
    cudaGetSymbolAddress((void**)&wr16, g_wr16);
    cudaGetSymbolAddress((void**)&wv16, g_wv16);
    cudaGetSymbolAddress((void**)&q16, g_q16);
    cudaGetSymbolAddress((void**)&k16, g_k16);
    cudaGetSymbolAddress((void**)&v16, g_v16);
    cudaGetSymbolAddress((void**)&s16, g_s16);
    cudaGetSymbolAddress((void**)&add16, g_add16);
    cudaGetSymbolAddress((void**)&psum, g_psum);

    cudaFuncSetAttribute(hgemm_projqk, cudaFuncAttributeMaxDynamicSharedMemorySize, SMEM_BYTES);
    cudaFuncSetAttribute(hgemm<false, 0, __half>, cudaFuncAttributeMaxDynamicSharedMemorySize, SMEM_BYTES);
    cudaFuncSetAttribute(hgemm<false, 1, __half>, cudaFuncAttributeMaxDynamicSharedMemorySize, SMEM_BYTES);
    cudaFuncSetAttribute(hgemm<true, 2, __half>,  cudaFuncAttributeMaxDynamicSharedMemorySize, SMEM_BYTES);

    // Streams + events (created once, outside capture).
    static cudaStream_t s2 = nullptr, s3 = nullptr;
    static cudaEvent_t evCvt = nullptr, evV = nullptr, evCopy = nullptr;
    if (!s2) {
        cudaStreamCreateWithFlags(&s2, cudaStreamNonBlocking);
        cudaStreamCreateWithFlags(&s3, cudaStreamNonBlocking);
        cudaEventCreateWithFlags(&evCvt, cudaEventDisableTiming);
        cudaEventCreateWithFlags(&evV, cudaEventDisableTiming);
        cudaEventCreateWithFlags(&evCopy, cudaEventDisableTiming);
    }

    dim3 blk(256);

    // --- all fp32->fp16 conversions in ONE launch
    cvt_all<<<dim3(2048, 1, 5), blk>>>(det_in, rel_in, W_det, W_rel, W_val,
                                       det16, rel16, wd16, wr16, wv16);
    cudaEventRecord(evCvt, 0);

    // --- stream 3: pass-through copy (independent; joined at the very end)
    cudaStreamWaitEvent(s3, evCvt, 0);   // fork from main so capture sees one root
    cudaMemcpyAsync(out, det_in, (size_t)ND * NB * DM * sizeof(float),
                    cudaMemcpyDeviceToDevice, s3);
    cudaEventRecord(evCopy, s3);

    // --- stream 2: V projection (starts right after cvt)
    cudaStreamWaitEvent(s2, evCvt, 0);
    dim3 gv(ND / 128, DF / 256, NB);
    hgemm<false, 0, __half><<<gv, blk, SMEM_BYTES, s2>>>(
        det16, wv16, v16, b_val, nullptr, 0L, 0.f, DM,
        (long)NB * DM, (long)DM, (long)DM, 0L, (long)DF, (long)ND * DF);
    cudaEventRecord(evV, s2);

    // --- main stream: Q+K projections (one launch, 512 CTAs)
    dim3 gqk(ND / 128, DF / 256, 2 * NB);
    hgemm_projqk<<<gqk, blk, SMEM_BYTES>>>(det16, rel16, wd16, wr16,
                                           b_det, b_rel, q16, k16);

    // --- scores (NT) with fused exp + partial row sums
    const float scl2 = (1.f / sqrtf((float)DF)) * 1.44269504f;  // log2(e)/sqrt(F)
    dim3 gs(NR / 128, ND / 256, NB);
    hgemm<false, 1, __half><<<gs, blk, SMEM_BYTES>>>(
        k16, q16, s16, nullptr, psum, (long)PSUM_BLKS * NR, scl2, DF,
        (long)DF, (long)NR * DF, (long)DF, (long)ND * DF, (long)ND, (long)NR * ND);

    // --- join: AV needs v16 from stream 2
    cudaStreamWaitEvent(0, evV, 0);

    // --- rel_add = (e @ v) / rowsum   (NN, fp16 out, fused normalization)
    dim3 ga(NR / 128, DF / 256, NB);
    hgemm<true, 2, __half><<<ga, blk, SMEM_BYTES>>>(
        s16, v16, add16, nullptr, psum, (long)PSUM_BLKS * NR, 0.f, ND,
        (long)ND, (long)NR * ND, (long)DF, (long)ND * DF, (long)DF, (long)NR * DF);

    // --- residual + LayerNorm (2 rows/block) -> out[Nd*B*D + ...]
    residual_ln<<<NB * NR / 2, 256>>>(add16, rel_in, gamma, beta,
                                      out + (size_t)ND * NB * DM);

    // --- join stream 3 before capture ends
    cudaStreamWaitEvent(0, evCopy, 0);
}

// round 14
// speedup vs baseline: 1.0201x; 1.0201x over previous
#include <cuda_runtime.h>
#include <cuda_fp16.h>
#include <cstdint>
#include <math.h>

// ---------------------------------------------------------------------------
// InteractionLayer via fp16 mma.sync m16n8k16 + 4-stage cp.async + ldmatrix
// (arch-portable PTX; harness targets plain sm_103 — no 'a' features).
// R14: exact R10 GEMM kernels + R10 s2 arrangement. New: scores and AV are
// split into batch halves; AV(0-3) runs on s2 concurrently with scores(4-7);
// LN(0-3) hides under AV(4-7). Softmax fused in GEMM epilogues.
// ---------------------------------------------------------------------------

#define ND 2048
#define NR 2048
#define NB 8
#define DM 512
#define DF 512
#define PSUM_BLKS 8   // scores gridDim.y = ND/256

// scratch (no cudaMalloc allowed)
__device__ __align__(16) __half g_det16[(size_t)ND * NB * DM];
__device__ __align__(16) __half g_rel16[(size_t)NR * NB * DM];
__device__ __align__(16) __half g_wd16[(size_t)DF * DM];
__device__ __align__(16) __half g_wr16[(size_t)DF * DM];
__device__ __align__(16) __half g_wv16[(size_t)DF * DM];
__device__ __align__(16) __half g_q16[(size_t)NB * ND * DF];
__device__ __align__(16) __half g_k16[(size_t)NB * NR * DF];
__device__ __align__(16) __half g_v16[(size_t)NB * ND * DF];
__device__ __align__(16) __half g_s16[(size_t)NB * NR * ND];    // exp weights
__device__ __align__(16) __half g_add16[(size_t)NB * NR * DF];  // rel_add
__device__ __align__(16) float  g_psum[(size_t)NB * PSUM_BLKS * NR];

__device__ __forceinline__ uint32_t smem_u32(const void* p) {
    uint32_t a;
    asm("{ .reg .u64 t; cvta.to.shared.u64 t, %1; cvt.u32.u64 %0, t; }" : "=r"(a) : "l"(p));
    return a;
}
__device__ __forceinline__ void cp16(uint32_t dst, const void* src) {
    asm volatile("cp.async.cg.shared.global [%0], [%1], 16;" :: "r"(dst), "l"(src) : "memory");
}
#define CP_COMMIT() asm volatile("cp.async.commit_group;" ::: "memory")

__device__ __forceinline__ void ldsm4(uint32_t* r, uint32_t a) {
    asm volatile("ldmatrix.sync.aligned.m8n8.x4.shared.b16 {%0,%1,%2,%3}, [%4];"
                 : "=r"(r[0]), "=r"(r[1]), "=r"(r[2]), "=r"(r[3]) : "r"(a));
}
__device__ __forceinline__ void ldsm4t(uint32_t* r, uint32_t a) {
    asm volatile("ldmatrix.sync.aligned.m8n8.x4.trans.shared.b16 {%0,%1,%2,%3}, [%4];"
                 : "=r"(r[0]), "=r"(r[1]), "=r"(r[2]), "=r"(r[3]) : "r"(a));
}
__device__ __forceinline__ float fex2(float x) {
    float r;
    asm("ex2.approx.f32 %0, %1;" : "=f"(r) : "f"(x));
    return r;
}

// smem halves per buffer (30720 B): As 128x40 (10240 B), Bs 20480 B
// (NT: 256x40; NN: 32x264). FOUR buffers: 122880 B.
#define AS_STRIDE 40
#define BNT_STRIDE 40
#define BNN_STRIDE 264
#define BUF_BYTES 30720
#define NSTAGE 4
#define SMEM_BYTES (NSTAGE * BUF_BYTES)

// ---------------------------------------------------------------------------
// Core GEMM body. 256 threads, 8 warps (2x4), warp tile 64x64, CTA 128x256.
// BNN=false (NT): C[m,n] = sum_k A[m*rsA+k] * B[n*rsB+k]
// BNN=true  (NN): C[m,n] = sum_k A[m*rsA+k] * B[k*rsB+n]
// EPI: 0 = bias add; 1 = exp(acc*escale) + partial row sums into aux;
//      2 = multiply by 1/(sum of PSUM_BLKS partials from aux).
// ---------------------------------------------------------------------------
template <bool BNN, int EPI, typename OutT>
__device__ __forceinline__ void gemm_body(
    const __half* __restrict__ A, const __half* __restrict__ B, OutT* __restrict__ C,
    const float* __restrict__ bias, float* __restrict__ aux, float escale,
    int K, long rsA, long rsB, long rsC)
{
    extern __shared__ __align__(16) char dyn[];
    const uint32_t sb = smem_u32(dyn);

    const int tid = threadIdx.x;
    const int wid = tid >> 5;
    const int lane = tid & 31;
    const int g = lane >> 2;
    const int c = lane & 3;
    const int t8 = lane >> 3;
    const int lr = lane & 7;
    const int wm = (wid >> 2) * 64;
    const int wn = (wid & 3) * 64;

    const long rowBase = (long)blockIdx.x * 128;
    const long colBase = (long)blockIdx.y * 256;

    float acc[4][8][4];
    #pragma unroll
    for (int mt = 0; mt < 4; mt++)
        #pragma unroll
        for (int nt = 0; nt < 8; nt++)
            #pragma unroll
            for (int r = 0; r < 4; r++) acc[mt][nt][r] = 0.f;

    const int NS = K / 32;

    auto issue = [&](int s) {
        const int buf = s % NSTAGE;
        const long k0 = (long)s * 32;
        const uint32_t ab = sb + buf * BUF_BYTES;
        const uint32_t bb = ab + 10240;
        #pragma unroll
        for (int i = 0; i < 2; i++) {
            const int idx = i * 256 + tid;
            const int row = idx >> 2, ch = idx & 3;
            cp16(ab + (row * AS_STRIDE + ch * 8) * 2,
                 &A[(rowBase + row) * rsA + k0 + ch * 8]);
        }
        if (BNN) {
            #pragma unroll
            for (int i = 0; i < 4; i++) {
                const int idx = i * 256 + tid;
                const int kr = idx >> 5, ch = idx & 31;
                cp16(bb + (kr * BNN_STRIDE + ch * 8) * 2,
                     &B[(k0 + kr) * rsB + colBase + ch * 8]);
            }
        } else {
            #pragma unroll
            for (int i = 0; i < 4; i++) {
                const int idx = i * 256 + tid;
                const int row = idx >> 2, ch = idx & 3;
                cp16(bb + (row * BNT_STRIDE + ch * 8) * 2,
                     &B[(colBase + row) * rsB + k0 + ch * 8]);
            }
        }
        CP_COMMIT();
    };

    issue(0);
    if (NS > 1) issue(1);
    if (NS > 2) issue(2);

    for (int s = 0; s < NS; s++) {
        if (s + 3 <= NS)
            asm volatile("cp.async.wait_group 2;" ::: "memory");
        else if (s + 2 == NS)
            asm volatile("cp.async.wait_group 1;" ::: "memory");
        else
            asm volatile("cp.async.wait_group 0;" ::: "memory");
        __syncthreads();

        const uint32_t ab = sb + (s % NSTAGE) * BUF_BYTES;
        const uint32_t bb = ab + 10240;

        #pragma unroll
        for (int kk = 0; kk < 2; kk++) {
            const int k0h = kk * 16;
            uint32_t a[4][4];
            #pragma unroll
            for (int mt = 0; mt < 4; mt++)
                ldsm4(a[mt], ab + ((wm + mt * 16 + (t8 & 1) * 8 + lr) * AS_STRIDE
                                   + k0h + (t8 >> 1) * 8) * 2);
            uint32_t b[4][4];
            #pragma unroll
            for (int np = 0; np < 4; np++) {
                if (BNN)
                    ldsm4t(b[np], bb + ((k0h + (t8 & 1) * 8 + lr) * BNN_STRIDE
                                        + wn + np * 16 + (t8 >> 1) * 8) * 2);
                else
                    ldsm4(b[np], bb + ((wn + np * 16 + (t8 >> 1) * 8 + lr) * BNT_STRIDE
                                       + k0h + (t8 & 1) * 8) * 2);
            }
            #pragma unroll
            for (int mt = 0; mt < 4; mt++)
                #pragma unroll
                for (int nt = 0; nt < 8; nt++)
                    asm volatile(
                        "mma.sync.aligned.m16n8k16.row.col.f32.f16.f16.f32 "
                        "{%0,%1,%2,%3}, {%4,%5,%6,%7}, {%8,%9}, {%0,%1,%2,%3};"
                        : "+f"(acc[mt][nt][0]), "+f"(acc[mt][nt][1]),
                          "+f"(acc[mt][nt][2]), "+f"(acc[mt][nt][3])
                        : "r"(a[mt][0]), "r"(a[mt][1]), "r"(a[mt][2]), "r"(a[mt][3]),
                          "r"(b[nt >> 1][(nt & 1) * 2]), "r"(b[nt >> 1][(nt & 1) * 2 + 1]));
        }
        if (s + 3 < NS) issue(s + 3);
    }

    const long nRowsTot = (long)gridDim.x * 128;

    // ---- epilogue
    float rsum[4][2];
    #pragma unroll
    for (int mt = 0; mt < 4; mt++) { rsum[mt][0] = 0.f; rsum[mt][1] = 0.f; }

    #pragma unroll
    for (int mt = 0; mt < 4; mt++) {
        const long row0 = rowBase + wm + mt * 16 + g;
        float sc0 = 1.f, sc1 = 1.f;
        if (EPI == 2) {
            float s0 = 0.f, s1 = 0.f;
            #pragma unroll
            for (int k = 0; k < PSUM_BLKS; k++) {
                s0 += aux[(long)k * nRowsTot + row0];
                s1 += aux[(long)k * nRowsTot + row0 + 8];
            }
            sc0 = 1.f / s0;
            sc1 = 1.f / s1;
        }
        #pragma unroll
        for (int nt = 0; nt < 8; nt++) {
            const long col = colBase + wn + nt * 8 + 2 * c;
            float x0 = acc[mt][nt][0], x1 = acc[mt][nt][1];
            float x2 = acc[mt][nt][2], x3 = acc[mt][nt][3];
            if (EPI == 0) {
                float bx = 0.f, by = 0.f;
                if (bias) { bx = bias[col]; by = bias[col + 1]; }
                x0 += bx; x1 += by; x2 += bx; x3 += by;
            } else if (EPI == 1) {
                x0 = fex2(x0 * escale); x1 = fex2(x1 * escale);
                x2 = fex2(x2 * escale); x3 = fex2(x3 * escale);
                rsum[mt][0] += x0 + x1;
                rsum[mt][1] += x2 + x3;
            } else {
                x0 *= sc0; x1 *= sc0; x2 *= sc1; x3 *= sc1;
            }
            if (sizeof(OutT) == 2) {
                *reinterpret_cast<__half2*>(C + row0 * rsC + col) = __floats2half2_rn(x0, x1);
                *reinterpret_cast<__half2*>(C + (row0 + 8) * rsC + col) = __floats2half2_rn(x2, x3);
            } else {
                *reinterpret_cast<float2*>((float*)C + row0 * rsC + col) = make_float2(x0, x1);
                *reinterpret_cast<float2*>((float*)C + (row0 + 8) * rsC + col) = make_float2(x2, x3);
            }
        }
    }

    if (EPI == 1) {
        float* sred = reinterpret_cast<float*>(dyn);   // [128 rows][4 n-warps]
        __syncthreads();
        #pragma unroll
        for (int mt = 0; mt < 4; mt++) {
            float v0 = rsum[mt][0], v1 = rsum[mt][1];
            v0 += __shfl_xor_sync(0xFFFFFFFFu, v0, 1);
            v0 += __shfl_xor_sync(0xFFFFFFFFu, v0, 2);
            v1 += __shfl_xor_sync(0xFFFFFFFFu, v1, 1);
            v1 += __shfl_xor_sync(0xFFFFFFFFu, v1, 2);
            if (c == 0) {
                const int rl = wm + mt * 16 + g;
                sred[rl * 4 + (wid & 3)] = v0;
                sred[(rl + 8) * 4 + (wid & 3)] = v1;
            }
        }
        __syncthreads();
        if (tid < 128) {
            const float s = sred[tid * 4] + sred[tid * 4 + 1]
                          + sred[tid * 4 + 2] + sred[tid * 4 + 3];
            aux[(long)blockIdx.y * nRowsTot + rowBase + tid] = s;
        }
    }
}

// Generic batched wrapper.
template <bool BNN, int EPI, typename OutT>
__global__ __launch_bounds__(256, 1) void hgemm(
    const __half* __restrict__ A, const __half* __restrict__ B, OutT* __restrict__ C,
    const float* __restrict__ bias, float* __restrict__ aux, long auxStride,
    float escale, int K,
    long rsA, long bsA, long rsB, long bsB, long rsC, long bsC)
{
    const int bz = blockIdx.z;
    gemm_body<BNN, EPI, OutT>(A + (long)bz * bsA, B + (long)bz * bsB,
                              C + (long)bz * bsC, bias,
                              aux ? aux + (long)bz * auxStride : nullptr,
                              escale, K, rsA, rsB, rsC);
}

// Q+K projections in one launch: z = which*NB + b.
__global__ __launch_bounds__(256, 1) void hgemm_projqk(
    const __half* __restrict__ det16, const __half* __restrict__ rel16,
    const __half* __restrict__ wd, const __half* __restrict__ wr,
    const float* __restrict__ bd, const float* __restrict__ br,
    __half* __restrict__ q16, __half* __restrict__ k16)
{
    const int z = blockIdx.z;
    const int which = z >> 3;
    const int b = z & 7;
    const __half* A = which ? rel16 : det16;
    const __half* W = which ? wr : wd;
    const float* bias = which ? br : bd;
    __half* C = which ? k16 : q16;
    gemm_body<false, 0, __half>(A + (long)b * DM, W, C + (long)b * ND * DF,
                                bias, nullptr, 0.f, DM, (long)NB * DM, DM, DF);
}

// ---------------------------------------------------------------------------
// One launch converting all five fp32 tensors to fp16.
// ---------------------------------------------------------------------------
__global__ __launch_bounds__(256) void cvt_all(
    const float* __restrict__ det, const float* __restrict__ rel,
    const float* __restrict__ wd, const float* __restrict__ wr,
    const float* __restrict__ wv,
    __half* __restrict__ det16, __half* __restrict__ rel16,
    __half* __restrict__ wd16, __half* __restrict__ wr16, __half* __restrict__ wv16)
{
    const float* src; __half* dst; long n;
    switch (blockIdx.z) {
        case 0: src = det; dst = det16; n = (long)ND * NB * DM; break;
        case 1: src = rel; dst = rel16; n = (long)NR * NB * DM; break;
        case 2: src = wd;  dst = wd16;  n = (long)DF * DM; break;
        case 3: src = wr;  dst = wr16;  n = (long)DF * DM; break;
        default: src = wv; dst = wv16;  n = (long)DF * DM; break;
    }
    long i = ((long)blockIdx.x * blockDim.x + threadIdx.x) * 4;
    const long stride = (long)gridDim.x * blockDim.x * 4;
    for (; i < n; i += stride) {
        float4 v = *reinterpret_cast<const float4*>(src + i);
        __half2* p = reinterpret_cast<__half2*>(dst + i);
        p[0] = __floats2half2_rn(v.x, v.y);
        p[1] = __floats2half2_rn(v.z, v.w);
    }
}

// ---------------------------------------------------------------------------
// out[r][b][:] = LN(add16[b][r][:] + rel_in[r][b][:]) * gamma + beta
// One 128-thread block per row; absolute row index = baseIdx + blockIdx.x.
// ---------------------------------------------------------------------------
__global__ __launch_bounds__(128) void residual_ln(
    const __half* __restrict__ add, const float* __restrict__ rel_in,
    const float* __restrict__ gamma, const float* __restrict__ beta,
    float* __restrict__ out, long baseIdx)
{
    const long idx = baseIdx + blockIdx.x;   // b*NR + r
    const long b = idx >> 11;
    const long r = idx & 2047;
    const int tid = threadIdx.x;
    const int f = tid * 4;

    uint2 araw = *reinterpret_cast<const uint2*>(&add[idx * DM + f]);
    const __half2* ah = reinterpret_cast<const __half2*>(&araw);
    float2 a01 = __half22float2(ah[0]);
    float2 a23 = __half22float2(ah[1]);
    const float4 r4 = *reinterpret_cast<const float4*>(&rel_in[(r * NB + b) * DM + f]);
    float x0 = a01.x + r4.x, x1 = a01.y + r4.y, x2 = a23.x + r4.z, x3 = a23.y + r4.w;

    float sum = x0 + x1 + x2 + x3;
    float ssq = x0 * x0 + x1 * x1 + x2 * x2 + x3 * x3;
    #pragma unroll
    for (int o = 16; o > 0; o >>= 1) {
        sum += __shfl_xor_sync(0xFFFFFFFFu, sum, o);
        ssq += __shfl_xor_sync(0xFFFFFFFFu, ssq, o);
    }
    __shared__ float s1[4], s2[4];
    const int w = tid >> 5;
    if ((tid & 31) == 0) { s1[w] = sum; s2[w] = ssq; }
    __syncthreads();
    sum = s1[0] + s1[1] + s1[2] + s1[3];
    ssq = s2[0] + s2[1] + s2[2] + s2[3];

    const float mean = sum * (1.f / DM);
    const float var = ssq * (1.f / DM) - mean * mean;
    const float rstd = rsqrtf(var + 1e-5f);

    const float4 g4 = *reinterpret_cast<const float4*>(&gamma[f]);
    const float4 be4 = *reinterpret_cast<const float4*>(&beta[f]);
    float4 o4;
    o4.x = (x0 - mean) * rstd * g4.x + be4.x;
    o4.y = (x1 - mean) * rstd * g4.y + be4.y;
    o4.z = (x2 - mean) * rstd * g4.z + be4.z;
    o4.w = (x3 - mean) * rstd * g4.w + be4.w;
    *reinterpret_cast<float4*>(&out[(r * NB + b) * DM + f]) = o4;
}

// ---------------------------------------------------------------------------
extern "C" void kernel_launch(void* const* d_in, const int* in_sizes, int n_in,
                              void* d_out, int out_size)
{
    const float* det_in = (const float*)d_in[0];
    const float* rel_in = (const float*)d_in[1];
    const float* W_det  = (const float*)d_in[2];
    const float* b_det  = (const float*)d_in[3];
    const float* W_rel  = (const float*)d_in[4];
    const float* b_rel  = (const float*)d_in[5];
    const float* W_val  = (const float*)d_in[6];
    const float* b_val  = (const float*)d_in[7];
    const float* gamma  = (const float*)d_in[8];
    const float* beta   = (const float*)d_in[9];
    float* out = (float*)d_out;

    __half *det16, *rel16, *wd16, *wr16, *wv16, *q16, *k16, *v16, *s16, *add16;
    float *psum;
    cudaGetSymbolAddress((void**)&det16, g_det16);
    cudaGetSymbolAddress((void**)&rel16, g_rel16);
    cudaGetSymbolAddress((void**)&wd16, g_wd16);
    cudaGetSymbolAddress((void**)&wr16, g_wr16);
    cudaGetSymbolAddress((void**)&wv16, g_wv16);
    cudaGetSymbolAddress((void**)&q16, g_q16);
    cudaGetSymbolAddress((void**)&k16, g_k16);
    cudaGetSymbolAddress((void**)&v16, g_v16);
    cudaGetSymbolAddress((void**)&s16, g_s16);
    cudaGetSymbolAddress((void**)&add16, g_add16);
    cudaGetSymbolAddress((void**)&psum, g_psum);

    cudaFuncSetAttribute(hgemm_projqk, cudaFuncAttributeMaxDynamicSharedMemorySize, SMEM_BYTES);
    cudaFuncSetAttribute(hgemm<false, 0, __half>, cudaFuncAttributeMaxDynamicSharedMemorySize, SMEM_BYTES);
    cudaFuncSetAttribute(hgemm<false, 1, __half>, cudaFuncAttributeMaxDynamicSharedMemorySize, SMEM_BYTES);
    cudaFuncSetAttribute(hgemm<true, 2, __half>,  cudaFuncAttributeMaxDynamicSharedMemorySize, SMEM_BYTES);

    // Streams + events (created once, outside capture).
    static cudaStream_t s2 = nullptr;
    static cudaEvent_t evCvt = nullptr, evV = nullptr, evSA = nullptr, evLNA = nullptr;
    if (!s2) {
        cudaStreamCreateWithFlags(&s2, cudaStreamNonBlocking);
        cudaEventCreateWithFlags(&evCvt, cudaEventDisableTiming);
        cudaEventCreateWithFlags(&evV, cudaEventDisableTiming);
        cudaEventCreateWithFlags(&evSA, cudaEventDisableTiming);
        cudaEventCreateWithFlags(&evLNA, cudaEventDisableTiming);
    }

    dim3 blk(256);
    const long halfQ = (long)4 * ND * DF;       // 4 batches of q16/k16/v16/add16
    const long halfS = (long)4 * NR * ND;       // 4 batches of s16
    const long halfP = (long)4 * PSUM_BLKS * NR;

    // --- all fp32->fp16 conversions in ONE launch (main)
    cvt_all<<<dim3(2048, 1, 5), blk>>>(det_in, rel_in, W_det, W_rel, W_val,
                                       det16, rel16, wd16, wr16, wv16);
    cudaEventRecord(evCvt, 0);

    // --- s2: pass-through copy, then V projection (R10 arrangement)
    cudaStreamWaitEvent(s2, evCvt, 0);
    cudaMemcpyAsync(out, det_in, (size_t)ND * NB * DM * sizeof(float),
                    cudaMemcpyDeviceToDevice, s2);
    dim3 gv(ND / 128, DF / 256, NB);
    hgemm<false, 0, __half><<<gv, blk, SMEM_BYTES, s2>>>(
        det16, wv16, v16, b_val, nullptr, 0L, 0.f, DM,
        (long)NB * DM, (long)DM, (long)DM, 0L, (long)DF, (long)ND * DF);
    cudaEventRecord(evV, s2);

    // --- main: Q+K projections (one launch, 512 CTAs)
    dim3 gqk(ND / 128, DF / 256, 2 * NB);
    hgemm_projqk<<<gqk, blk, SMEM_BYTES>>>(det16, rel16, wd16, wr16,
                                           b_det, b_rel, q16, k16);

    const float scl2 = (1.f / sqrtf((float)DF)) * 1.44269504f;  // log2(e)/sqrt(F)
    dim3 gs(NR / 128, ND / 256, 4);          // half the batches per launch
    dim3 ga(NR / 128, DF / 256, 4);

    // --- scores A (batches 0-3) on main
    hgemm<false, 1, __half><<<gs, blk, SMEM_BYTES>>>(
        k16, q16, s16, nullptr, psum, (long)PSUM_BLKS * NR, scl2, DF,
        (long)DF, (long)NR * DF, (long)DF, (long)ND * DF, (long)ND, (long)NR * ND);
    cudaEventRecord(evSA, 0);

    // --- scores B (batches 4-7) on main (co-runs with AV_A below)
    hgemm<false, 1, __half><<<gs, blk, SMEM_BYTES>>>(
        k16 + halfQ, q16 + halfQ, s16 + halfS, nullptr, psum + halfP,
        (long)PSUM_BLKS * NR, scl2, DF,
        (long)DF, (long)NR * DF, (long)DF, (long)ND * DF, (long)ND, (long)NR * ND);

    // --- s2: AV_A (batches 0-3) after scores_A; then LN_A (hidden under AV_B)
    cudaStreamWaitEvent(s2, evSA, 0);
    hgemm<true, 2, __half><<<ga, blk, SMEM_BYTES, s2>>>(
        s16, v16, add16, nullptr, psum, (long)PSUM_BLKS * NR, 0.f, ND,
        (long)ND, (long)NR * ND, (long)DF, (long)ND * DF, (long)DF, (long)NR * DF);
    residual_ln<<<4 * NR, 128, 0, s2>>>(add16, rel_in, gamma, beta,
                                        out + (size_t)ND * NB * DM, 0L);
    cudaEventRecord(evLNA, s2);

    // --- main: AV_B (batches 4-7; needs v16) then LN_B
    cudaStreamWaitEvent(0, evV, 0);
    hgemm<true, 2, __half><<<ga, blk, SMEM_BYTES>>>(
        s16 + halfS, v16 + halfQ, add16 + halfQ, nullptr, psum + halfP,
        (long)PSUM_BLKS * NR, 0.f, ND,
        (long)ND, (long)NR * ND, (long)DF, (long)ND * DF, (long)DF, (long)NR * DF);
    residual_ln<<<4 * NR, 128>>>(add16, rel_in, gamma, beta,
                                 out + (size_t)ND * NB * DM, (long)4 * NR);

    // --- join s2 before capture ends
    cudaStreamWaitEvent(0, evLNA, 0);
}

// round 15
// speedup vs baseline: 1.0706x; 1.0496x over previous
#include <cuda_runtime.h>
#include <cuda_fp16.h>
#include <cstdint>
#include <math.h>

// ---------------------------------------------------------------------------
// InteractionLayer via fp16 mma.sync m16n8k16 + 4-stage cp.async + ldmatrix
// (arch-portable PTX; harness targets plain sm_103 — no 'a' features).
// R15: 2 CTAs/SM. CTA tile 128x128, 8 warps (2x4) of 64x32, BK=32, NSTAGE=4
// (80 KB smem/CTA), __launch_bounds__(256,2) -> 4 warps/SMSP hides LDSM
// latency. Schedule identical to R10. Softmax fused in GEMM epilogues.
// ---------------------------------------------------------------------------

#define ND 2048
#define NR 2048
#define NB 8
#define DM 512
#define DF 512
#define PSUM_BLKS 16   // scores gridDim.y = ND/128

// scratch (no cudaMalloc allowed)
__device__ __align__(16) __half g_det16[(size_t)ND * NB * DM];
__device__ __align__(16) __half g_rel16[(size_t)NR * NB * DM];
__device__ __align__(16) __half g_wd16[(size_t)DF * DM];
__device__ __align__(16) __half g_wr16[(size_t)DF * DM];
__device__ __align__(16) __half g_wv16[(size_t)DF * DM];
__device__ __align__(16) __half g_q16[(size_t)NB * ND * DF];
__device__ __align__(16) __half g_k16[(size_t)NB * NR * DF];
__device__ __align__(16) __half g_v16[(size_t)NB * ND * DF];
__device__ __align__(16) __half g_s16[(size_t)NB * NR * ND];    // exp weights
__device__ __align__(16) __half g_add16[(size_t)NB * NR * DF];  // rel_add
__device__ __align__(16) float  g_psum[(size_t)NB * PSUM_BLKS * NR];

__device__ __forceinline__ uint32_t smem_u32(const void* p) {
    uint32_t a;
    asm("{ .reg .u64 t; cvta.to.shared.u64 t, %1; cvt.u32.u64 %0, t; }" : "=r"(a) : "l"(p));
    return a;
}
__device__ __forceinline__ void cp16(uint32_t dst, const void* src) {
    asm volatile("cp.async.cg.shared.global [%0], [%1], 16;" :: "r"(dst), "l"(src) : "memory");
}
#define CP_COMMIT() asm volatile("cp.async.commit_group;" ::: "memory")

__device__ __forceinline__ void ldsm4(uint32_t* r, uint32_t a) {
    asm volatile("ldmatrix.sync.aligned.m8n8.x4.shared.b16 {%0,%1,%2,%3}, [%4];"
                 : "=r"(r[0]), "=r"(r[1]), "=r"(r[2]), "=r"(r[3]) : "r"(a));
}
__device__ __forceinline__ void ldsm4t(uint32_t* r, uint32_t a) {
    asm volatile("ldmatrix.sync.aligned.m8n8.x4.trans.shared.b16 {%0,%1,%2,%3}, [%4];"
                 : "=r"(r[0]), "=r"(r[1]), "=r"(r[2]), "=r"(r[3]) : "r"(a));
}
__device__ __forceinline__ float fex2(float x) {
    float r;
    asm("ex2.approx.f32 %0, %1;" : "=f"(r) : "f"(x));
    return r;
}

// Per-buffer smem (20480 B): A 128x40 halves (10240 B); B: NT 128x40 halves
// (10240 B) / NN 32x136 halves (8704 B, padded). FOUR buffers: 81920 B.
// Bank patterns: stride 40 halves -> 16B-bank = 5r mod 32 (conflict-free for
// 8-row ldmatrix groups); stride 136 -> 17r mod 32 (conflict-free).
#define AS_STRIDE 40
#define BNT_STRIDE 40
#define BNN_STRIDE 136
#define BUF_BYTES 20480
#define NSTAGE 4
#define SMEM_BYTES (NSTAGE * BUF_BYTES)

// ---------------------------------------------------------------------------
// Core GEMM body. 256 threads, 8 warps (2x4), warp tile 64x32, CTA 128x128.
// BNN=false (NT): C[m,n] = sum_k A[m*rsA+k] * B[n*rsB+k]
// BNN=true  (NN): C[m,n] = sum_k A[m*rsA+k] * B[k*rsB+n]
// EPI: 0 = bias add; 1 = exp(acc*escale) + partial row sums into aux
//      (aux[blockIdx.y * nRowsTot + row]); 2 = multiply by
//      1/(sum of PSUM_BLKS partials from aux).
// ---------------------------------------------------------------------------
template <bool BNN, int EPI, typename OutT>
__device__ __forceinline__ void gemm_body(
    const __half* __restrict__ A, const __half* __restrict__ B, OutT* __restrict__ C,
    const float* __restrict__ bias, float* __restrict__ aux, float escale,
    int K, long rsA, long rsB, long rsC)
{
    extern __shared__ __align__(16) char dyn[];
    const uint32_t sb = smem_u32(dyn);

    const int tid = threadIdx.x;
    const int wid = tid >> 5;
    const int lane = tid & 31;
    const int g = lane >> 2;
    const int c = lane & 3;
    const int t8 = lane >> 3;
    const int lr = lane & 7;
    const int wm = (wid >> 2) * 64;     // warp m: 0/64
    const int wn = (wid & 3) * 32;      // warp n: 0..96

    const long rowBase = (long)blockIdx.x * 128;
    const long colBase = (long)blockIdx.y * 128;

    float acc[4][4][4];
    #pragma unroll
    for (int mt = 0; mt < 4; mt++)
        #pragma unroll
        for (int nt = 0; nt < 4; nt++)
            #pragma unroll
            for (int r = 0; r < 4; r++) acc[mt][nt][r] = 0.f;

    const int NS = K / 32;

    auto issue = [&](int s) {
        const int buf = s % NSTAGE;
        const long k0 = (long)s * 32;
        const uint32_t ab = sb + buf * BUF_BYTES;
        const uint32_t bb = ab + 10240;
        #pragma unroll
        for (int i = 0; i < 2; i++) {   // A: 128 rows x 4 chunks = 512 cp16
            const int idx = i * 256 + tid;
            const int row = idx >> 2, ch = idx & 3;
            cp16(ab + (row * AS_STRIDE + ch * 8) * 2,
                 &A[(rowBase + row) * rsA + k0 + ch * 8]);
        }
        if (BNN) {                      // B: 32 k-rows x 16 chunks = 512 cp16
            #pragma unroll
            for (int i = 0; i < 2; i++) {
                const int idx = i * 256 + tid;
                const int kr = idx >> 4, ch = idx & 15;
                cp16(bb + (kr * BNN_STRIDE + ch * 8) * 2,
                     &B[(k0 + kr) * rsB + colBase + ch * 8]);
            }
        } else {                        // B: 128 rows x 4 chunks = 512 cp16
            #pragma unroll
            for (int i = 0; i < 2; i++) {
                const int idx = i * 256 + tid;
                const int row = idx >> 2, ch = idx & 3;
                cp16(bb + (row * BNT_STRIDE + ch * 8) * 2,
                     &B[(colBase + row) * rsB + k0 + ch * 8]);
            }
        }
        CP_COMMIT();
    };

    issue(0);
    if (NS > 1) issue(1);
    if (NS > 2) issue(2);

    for (int s = 0; s < NS; s++) {
        if (s + 3 <= NS)
            asm volatile("cp.async.wait_group 2;" ::: "memory");
        else if (s + 2 == NS)
            asm volatile("cp.async.wait_group 1;" ::: "memory");
        else
            asm volatile("cp.async.wait_group 0;" ::: "memory");
        __syncthreads();

        const uint32_t ab = sb + (s % NSTAGE) * BUF_BYTES;
        const uint32_t bb = ab + 10240;

        #pragma unroll
        for (int kk = 0; kk < 2; kk++) {
            const int k0h = kk * 16;
            uint32_t a[4][4];
            #pragma unroll
            for (int mt = 0; mt < 4; mt++)
                ldsm4(a[mt], ab + ((wm + mt * 16 + (t8 & 1) * 8 + lr) * AS_STRIDE
                                   + k0h + (t8 >> 1) * 8) * 2);
            uint32_t b[2][4];
            #pragma unroll
            for (int np = 0; np < 2; np++) {
                if (BNN)
                    ldsm4t(b[np], bb + ((k0h + (t8 & 1) * 8 + lr) * BNN_STRIDE
                                        + wn + np * 16 + (t8 >> 1) * 8) * 2);
                else
                    ldsm4(b[np], bb + ((wn + np * 16 + (t8 >> 1) * 8 + lr) * BNT_STRIDE
                                       + k0h + (t8 & 1) * 8) * 2);
            }
            #pragma unroll
            for (int mt = 0; mt < 4; mt++)
                #pragma unroll
                for (int nt = 0; nt < 4; nt++)
                    asm volatile(
                        "mma.sync.aligned.m16n8k16.row.col.f32.f16.f16.f32 "
                        "{%0,%1,%2,%3}, {%4,%5,%6,%7}, {%8,%9}, {%0,%1,%2,%3};"
                        : "+f"(acc[mt][nt][0]), "+f"(acc[mt][nt][1]),
                          "+f"(acc[mt][nt][2]), "+f"(acc[mt][nt][3])
                        : "r"(a[mt][0]), "r"(a[mt][1]), "r"(a[mt][2]), "r"(a[mt][3]),
                          "r"(b[nt >> 1][(nt & 1) * 2]), "r"(b[nt >> 1][(nt & 1) * 2 + 1]));
        }
        if (s + 3 < NS) issue(s + 3);
    }

    const long nRowsTot = (long)gridDim.x * 128;

    // ---- epilogue
    float rsum[4][2];
    #pragma unroll
    for (int mt = 0; mt < 4; mt++) { rsum[mt][0] = 0.f; rsum[mt][1] = 0.f; }

    #pragma unroll
    for (int mt = 0; mt < 4; mt++) {
        const long row0 = rowBase + wm + mt * 16 + g;
        float sc0 = 1.f, sc1 = 1.f;
        if (EPI == 2) {
            float s0 = 0.f, s1 = 0.f;
            #pragma unroll
            for (int k = 0; k < PSUM_BLKS; k++) {
                s0 += aux[(long)k * nRowsTot + row0];
                s1 += aux[(long)k * nRowsTot + row0 + 8];
            }
            sc0 = 1.f / s0;
            sc1 = 1.f / s1;
        }
        #pragma unroll
        for (int nt = 0; nt < 4; nt++) {
            const long col = colBase + wn + nt * 8 + 2 * c;
            float x0 = acc[mt][nt][0], x1 = acc[mt][nt][1];
            float x2 = acc[mt][nt][2], x3 = acc[mt][nt][3];
            if (EPI == 0) {
                float bx = 0.f, by = 0.f;
                if (bias) { bx = bias[col]; by = bias[col + 1]; }
                x0 += bx; x1 += by; x2 += bx; x3 += by;
            } else if (EPI == 1) {
                x0 = fex2(x0 * escale); x1 = fex2(x1 * escale);
                x2 = fex2(x2 * escale); x3 = fex2(x3 * escale);
                rsum[mt][0] += x0 + x1;
                rsum[mt][1] += x2 + x3;
            } else {
                x0 *= sc0; x1 *= sc0; x2 *= sc1; x3 *= sc1;
            }
            if (sizeof(OutT) == 2) {
                *reinterpret_cast<__half2*>(C + row0 * rsC + col) = __floats2half2_rn(x0, x1);
                *reinterpret_cast<__half2*>(C + (row0 + 8) * rsC + col) = __floats2half2_rn(x2, x3);
            } else {
                *reinterpret_cast<float2*>((float*)C + row0 * rsC + col) = make_float2(x0, x1);
                *reinterpret_cast<float2*>((float*)C + (row0 + 8) * rsC + col) = make_float2(x2, x3);
            }
        }
    }

    if (EPI == 1) {
        float* sred = reinterpret_cast<float*>(dyn);   // [128 rows][4 n-warps]
        __syncthreads();
        #pragma unroll
        for (int mt = 0; mt < 4; mt++) {
            float v0 = rsum[mt][0], v1 = rsum[mt][1];
            v0 += __shfl_xor_sync(0xFFFFFFFFu, v0, 1);
            v0 += __shfl_xor_sync(0xFFFFFFFFu, v0, 2);
            v1 += __shfl_xor_sync(0xFFFFFFFFu, v1, 1);
            v1 += __shfl_xor_sync(0xFFFFFFFFu, v1, 2);
            if (c == 0) {
                const int rl = wm + mt * 16 + g;
                sred[rl * 4 + (wid & 3)] = v0;
                sred[(rl + 8) * 4 + (wid & 3)] = v1;
            }
        }
        __syncthreads();
        if (tid < 128) {
            const float s = sred[tid * 4] + sred[tid * 4 + 1]
                          + sred[tid * 4 + 2] + sred[tid * 4 + 3];
            aux[(long)blockIdx.y * nRowsTot + rowBase + tid] = s;
        }
    }
}

// Generic batched wrapper.
template <bool BNN, int EPI, typename OutT>
__global__ __launch_bounds__(256, 2) void hgemm(
    const __half* __restrict__ A, const __half* __restrict__ B, OutT* __restrict__ C,
    const float* __restrict__ bias, float* __restrict__ aux, long auxStride,
    float escale, int K,
    long rsA, long bsA, long rsB, long bsB, long rsC, long bsC)
{
    const int bz = blockIdx.z;
    gemm_body<BNN, EPI, OutT>(A + (long)bz * bsA, B + (long)bz * bsB,
                              C + (long)bz * bsC, bias,
                              aux ? aux + (long)bz * auxStride : nullptr,
                              escale, K, rsA, rsB, rsC);
}

// Q+K projections in one launch: z = which*NB + b.
__global__ __launch_bounds__(256, 2) void hgemm_projqk(
    const __half* __restrict__ det16, const __half* __restrict__ rel16,
    const __half* __restrict__ wd, const __half* __restrict__ wr,
    const float* __restrict__ bd, const float* __restrict__ br,
    __half* __restrict__ q16, __half* __restrict__ k16)
{
    const int z = blockIdx.z;
    const int which = z >> 3;
    const int b = z & 7;
    const __half* A = which ? rel16 : det16;
    const __half* W = which ? wr : wd;
    const float* bias = which ? br : bd;
    __half* C = which ? k16 : q16;
    gemm_body<false, 0, __half>(A + (long)b * DM, W, C + (long)b * ND * DF,
                                bias, nullptr, 0.f, DM, (long)NB * DM, DM, DF);
}

// ---------------------------------------------------------------------------
// One launch converting all five fp32 tensors to fp16.
// ---------------------------------------------------------------------------
__global__ __launch_bounds__(256) void cvt_all(
    const float* __restrict__ det, const float* __restrict__ rel,
    const float* __restrict__ wd, const float* __restrict__ wr,
    const float* __restrict__ wv,
    __half* __restrict__ det16, __half* __restrict__ rel16,
    __half* __restrict__ wd16, __half* __restrict__ wr16, __half* __restrict__ wv16)
{
    const float* src; __half* dst; long n;
    switch (blockIdx.z) {
        case 0: src = det; dst = det16; n = (long)ND * NB * DM; break;
        case 1: src = rel; dst = rel16; n = (long)NR * NB * DM; break;
        case 2: src = wd;  dst = wd16;  n = (long)DF * DM; break;
        case 3: src = wr;  dst = wr16;  n = (long)DF * DM; break;
        default: src = wv; dst = wv16;  n = (long)DF * DM; break;
    }
    long i = ((long)blockIdx.x * blockDim.x + threadIdx.x) * 4;
    const long stride = (long)gridDim.x * blockDim.x * 4;
    for (; i < n; i += stride) {
        float4 v = *reinterpret_cast<const float4*>(src + i);
        __half2* p = reinterpret_cast<__half2*>(dst + i);
        p[0] = __floats2half2_rn(v.x, v.y);
        p[1] = __floats2half2_rn(v.z, v.w);
    }
}

// ---------------------------------------------------------------------------
// out[r][b][:] = LN(add16[b][r][:] + rel_in[r][b][:]) * gamma + beta
// ---------------------------------------------------------------------------
__global__ __launch_bounds__(128) void residual_ln(
    const __half* __restrict__ add, const float* __restrict__ rel_in,
    const float* __restrict__ gamma, const float* __restrict__ beta,
    float* __restrict__ out)
{
    const long idx = blockIdx.x;          // b*NR + r
    const long b = idx >> 11;
    const long r = idx & 2047;
    const int tid = threadIdx.x;
    const int f = tid * 4;

    uint2 araw = *reinterpret_cast<const uint2*>(&add[idx * DM + f]);
    const __half2* ah = reinterpret_cast<const __half2*>(&araw);
    float2 a01 = __half22float2(ah[0]);
    float2 a23 = __half22float2(ah[1]);
    const float4 r4 = *reinterpret_cast<const float4*>(&rel_in[(r * NB + b) * DM + f]);
    float x0 = a01.x + r4.x, x1 = a01.y + r4.y, x2 = a23.x + r4.z, x3 = a23.y + r4.w;

    float sum = x0 + x1 + x2 + x3;
    float ssq = x0 * x0 + x1 * x1 + x2 * x2 + x3 * x3;
    #pragma unroll
    for (int o = 16; o > 0; o >>= 1) {
        sum += __shfl_xor_sync(0xFFFFFFFFu, sum, o);
        ssq += __shfl_xor_sync(0xFFFFFFFFu, ssq, o);
    }
    __shared__ float s1[4], s2[4];
    const int w = tid >> 5;
    if ((tid & 31) == 0) { s1[w] = sum; s2[w] = ssq; }
    __syncthreads();
    sum = s1[0] + s1[1] + s1[2] + s1[3];
    ssq = s2[0] + s2[1] + s2[2] + s2[3];

    const float mean = sum * (1.f / DM);
    const float var = ssq * (1.f / DM) - mean * mean;
    const float rstd = rsqrtf(var + 1e-5f);

    const float4 g4 = *reinterpret_cast<const float4*>(&gamma[f]);
    const float4 be4 = *reinterpret_cast<const float4*>(&beta[f]);
    float4 o4;
    o4.x = (x0 - mean) * rstd * g4.x + be4.x;
    o4.y = (x1 - mean) * rstd * g4.y + be4.y;
    o4.z = (x2 - mean) * rstd * g4.z + be4.z;
    o4.w = (x3 - mean) * rstd * g4.w + be4.w;
    *reinterpret_cast<float4*>(&out[(r * NB + b) * DM + f]) = o4;
}

// ---------------------------------------------------------------------------
extern "C" void kernel_launch(void* const* d_in, const int* in_sizes, int n_in,
                              void* d_out, int out_size)
{
    const float* det_in = (const float*)d_in[0];
    const float* rel_in = (const float*)d_in[1];
    const float* W_det  = (const float*)d_in[2];
    const float* b_det  = (const float*)d_in[3];
    const float* W_rel  = (const float*)d_in[4];
    const float* b_rel  = (const float*)d_in[5];
    const float* W_val  = (const float*)d_in[6];
    const float* b_val  = (const float*)d_in[7];
    const float* gamma  = (const float*)d_in[8];
    const float* beta   = (const float*)d_in[9];
    float* out = (float*)d_out;

    __half *det16, *rel16, *wd16, *wr16, *wv16, *q16, *k16, *v16, *s16, *add16;
    float *psum;
    cudaGetSymbolAddress((void**)&det16, g_det16);
    cudaGetSymbolAddress((void**)&rel16, g_rel16);
    cudaGetSymbolAddress((void**)&wd16, g_wd16);
    cudaGetSymbolAddress((void**)&wr16, g_wr16);
    cudaGetSymbolAddress((void**)&wv16, g_wv16);
    cudaGetSymbolAddress((void**)&q16, g_q16);
    cudaGetSymbolAddress((void**)&k16, g_k16);
    cudaGetSymbolAddress((void**)&v16, g_v16);
    cudaGetSymbolAddress((void**)&s16, g_s16);
    cudaGetSymbolAddress((void**)&add16, g_add16);
    cudaGetSymbolAddress((void**)&psum, g_psum);

    cudaFuncSetAttribute(hgemm_projqk, cudaFuncAttributeMaxDynamicSharedMemorySize, SMEM_BYTES);
    cudaFuncSetAttribute(hgemm<false, 0, __half>, cudaFuncAttributeMaxDynamicSharedMemorySize, SMEM_BYTES);
    cudaFuncSetAttribute(hgemm<false, 1, __half>, cudaFuncAttributeMaxDynamicSharedMemorySize, SMEM_BYTES);
    cudaFuncSetAttribute(hgemm<true, 2, __half>,  cudaFuncAttributeMaxDynamicSharedMemorySize, SMEM_BYTES);

    // Side stream + events (created once, outside capture).
    static cudaStream_t s2 = nullptr;
    static cudaEvent_t evCvt = nullptr, evV = nullptr;
    if (!s2) {
        cudaStreamCreateWithFlags(&s2, cudaStreamNonBlocking);
        cudaEventCreateWithFlags(&evCvt, cudaEventDisableTiming);
        cudaEventCreateWithFlags(&evV, cudaEventDisableTiming);
    }

    dim3 blk(256);

    // --- all fp32->fp16 conversions in ONE launch
    cvt_all<<<dim3(2048, 1, 5), blk>>>(det_in, rel_in, W_det, W_rel, W_val,
                                       det16, rel16, wd16, wr16, wv16);
    cudaEventRecord(evCvt, 0);

    // --- side stream: pass-through copy + V projection
    cudaStreamWaitEvent(s2, evCvt, 0);
    cudaMemcpyAsync(out, det_in, (size_t)ND * NB * DM * sizeof(float),
                    cudaMemcpyDeviceToDevice, s2);
    dim3 gv(ND / 128, DF / 128, NB);
    hgemm<false, 0, __half><<<gv, blk, SMEM_BYTES, s2>>>(
        det16, wv16, v16, b_val, nullptr, 0L, 0.f, DM,
        (long)NB * DM, (long)DM, (long)DM, 0L, (long)DF, (long)ND * DF);
    cudaEventRecord(evV, s2);

    // --- main stream: Q+K projections (one launch, 1024 CTAs)
    dim3 gqk(ND / 128, DF / 128, 2 * NB);
    hgemm_projqk<<<gqk, blk, SMEM_BYTES>>>(det16, rel16, wd16, wr16,
                                           b_det, b_rel, q16, k16);

    // --- scores (NT) with fused exp + partial row sums (2048 CTAs)
    const float scl2 = (1.f / sqrtf((float)DF)) * 1.44269504f;  // log2(e)/sqrt(F)
    dim3 gs(NR / 128, ND / 128, NB);
    hgemm<false, 1, __half><<<gs, blk, SMEM_BYTES>>>(
        k16, q16, s16, nullptr, psum, (long)PSUM_BLKS * NR, scl2, DF,
        (long)DF, (long)NR * DF, (long)DF, (long)ND * DF, (long)ND, (long)NR * ND);

    // --- join: AV needs v16 from the side stream
    cudaStreamWaitEvent(0, evV, 0);

    // --- rel_add = (e @ v) / rowsum   (NN, fp16 out, 512 CTAs)
    dim3 ga(NR / 128, DF / 128, NB);
    hgemm<true, 2, __half><<<ga, blk, SMEM_BYTES>>>(
        s16, v16, add16, nullptr, psum, (long)PSUM_BLKS * NR, 0.f, ND,
        (long)ND, (long)NR * ND, (long)DF, (long)ND * DF, (long)DF, (long)NR * DF);

    // --- residual + LayerNorm -> out[Nd*B*D + ...]
    residual_ln<<<NB * NR, 128>>>(add16, rel_in, gamma, beta,
                                  out + (size_t)ND * NB * DM);
}

// round 16
// speedup vs baseline: 1.0922x; 1.0201x over previous
#include <cuda_runtime.h>
#include <cuda_fp16.h>
#include <cstdint>
#include <math.h>

// ---------------------------------------------------------------------------
// InteractionLayer via fp16 mma.sync m16n8k16 + 4-stage cp.async + ldmatrix
// (arch-portable PTX; harness targets plain sm_103 — no 'a' features).
// R16: R15 GEMM config (128x128 CTA, 2 CTAs/SM) unchanged. New:
//  - AV epilogue adds the rel16 residual (split 0) before fp16 store
//  - AV split-K=2 (1024 CTAs; wave waste 27% -> 13%), partials summed in LN
//  - LN reads only the two fp16 partials (no fp32 rel_in read), 2 rows/block
// Softmax stays fused in GEMM epilogues.
// ---------------------------------------------------------------------------

#define ND 2048
#define NR 2048
#define NB 8
#define DM 512
#define DF 512
#define PSUM_BLKS 16   // scores gridDim.y = ND/128
#define KSPLIT 2       // AV split-K factor

// scratch (no cudaMalloc allowed)
__device__ __align__(16) __half g_det16[(size_t)ND * NB * DM];
__device__ __align__(16) __half g_rel16[(size_t)NR * NB * DM];
__device__ __align__(16) __half g_wd16[(size_t)DF * DM];
__device__ __align__(16) __half g_wr16[(size_t)DF * DM];
__device__ __align__(16) __half g_wv16[(size_t)DF * DM];
__device__ __align__(16) __half g_q16[(size_t)NB * ND * DF];
__device__ __align__(16) __half g_k16[(size_t)NB * NR * DF];
__device__ __align__(16) __half g_v16[(size_t)NB * ND * DF];
__device__ __align__(16) __half g_s16[(size_t)NB * NR * ND];    // exp weights
__device__ __align__(16) __half g_part[(size_t)KSPLIT * NB * NR * DF]; // AV partials
__device__ __align__(16) float  g_psum[(size_t)NB * PSUM_BLKS * NR];

__device__ __forceinline__ uint32_t smem_u32(const void* p) {
    uint32_t a;
    asm("{ .reg .u64 t; cvta.to.shared.u64 t, %1; cvt.u32.u64 %0, t; }" : "=r"(a) : "l"(p));
    return a;
}
__device__ __forceinline__ void cp16(uint32_t dst, const void* src) {
    asm volatile("cp.async.cg.shared.global [%0], [%1], 16;" :: "r"(dst), "l"(src) : "memory");
}
#define CP_COMMIT() asm volatile("cp.async.commit_group;" ::: "memory")

__device__ __forceinline__ void ldsm4(uint32_t* r, uint32_t a) {
    asm volatile("ldmatrix.sync.aligned.m8n8.x4.shared.b16 {%0,%1,%2,%3}, [%4];"
                 : "=r"(r[0]), "=r"(r[1]), "=r"(r[2]), "=r"(r[3]) : "r"(a));
}
__device__ __forceinline__ void ldsm4t(uint32_t* r, uint32_t a) {
    asm volatile("ldmatrix.sync.aligned.m8n8.x4.trans.shared.b16 {%0,%1,%2,%3}, [%4];"
                 : "=r"(r[0]), "=r"(r[1]), "=r"(r[2]), "=r"(r[3]) : "r"(a));
}
__device__ __forceinline__ float fex2(float x) {
    float r;
    asm("ex2.approx.f32 %0, %1;" : "=f"(r) : "f"(x));
    return r;
}

// Per-buffer smem (20480 B): A 128x40 halves; B: NT 128x40 / NN 32x136.
#define AS_STRIDE 40
#define BNT_STRIDE 40
#define BNN_STRIDE 136
#define BUF_BYTES 20480
#define NSTAGE 4
#define SMEM_BYTES (NSTAGE * BUF_BYTES)

// ---------------------------------------------------------------------------
// Core GEMM body. 256 threads, 8 warps (2x4), warp tile 64x32, CTA 128x128.
// EPI: 0 = bias add; 1 = exp(acc*escale) + partial row sums into aux;
//      2 = multiply by 1/(sum of PSUM_BLKS partials) and optionally add
//          residual resid[row*rsResid + col] (fp16).
// ---------------------------------------------------------------------------
template <bool BNN, int EPI, typename OutT>
__device__ __forceinline__ void gemm_body(
    const __half* __restrict__ A, const __half* __restrict__ B, OutT* __restrict__ C,
    const float* __restrict__ bias, float* __restrict__ aux, float escale,
    const __half* __restrict__ resid, long rsResid,
    int K, long rsA, long rsB, long rsC)
{
    extern __shared__ __align__(16) char dyn[];
    const uint32_t sb = smem_u32(dyn);

    const int tid = threadIdx.x;
    const int wid = tid >> 5;
    const int lane = tid & 31;
    const int g = lane >> 2;
    const int c = lane & 3;
    const int t8 = lane >> 3;
    const int lr = lane & 7;
    const int wm = (wid >> 2) * 64;
    const int wn = (wid & 3) * 32;

    const long rowBase = (long)blockIdx.x * 128;
    const long colBase = (long)blockIdx.y * 128;

    float acc[4][4][4];
    #pragma unroll
    for (int mt = 0; mt < 4; mt++)
        #pragma unroll
        for (int nt = 0; nt < 4; nt++)
            #pragma unroll
            for (int r = 0; r < 4; r++) acc[mt][nt][r] = 0.f;

    const int NS = K / 32;

    auto issue = [&](int s) {
        const int buf = s % NSTAGE;
        const long k0 = (long)s * 32;
        const uint32_t ab = sb + buf * BUF_BYTES;
        const uint32_t bb = ab + 10240;
        #pragma unroll
        for (int i = 0; i < 2; i++) {
            const int idx = i * 256 + tid;
            const int row = idx >> 2, ch = idx & 3;
            cp16(ab + (row * AS_STRIDE + ch * 8) * 2,
                 &A[(rowBase + row) * rsA + k0 + ch * 8]);
        }
        if (BNN) {
            #pragma unroll
            for (int i = 0; i < 2; i++) {
                const int idx = i * 256 + tid;
                const int kr = idx >> 4, ch = idx & 15;
                cp16(bb + (kr * BNN_STRIDE + ch * 8) * 2,
                     &B[(k0 + kr) * rsB + colBase + ch * 8]);
            }
        } else {
            #pragma unroll
            for (int i = 0; i < 2; i++) {
                const int idx = i * 256 + tid;
                const int row = idx >> 2, ch = idx & 3;
                cp16(bb + (row * BNT_STRIDE + ch * 8) * 2,
                     &B[(colBase + row) * rsB + k0 + ch * 8]);
            }
        }
        CP_COMMIT();
    };

    issue(0);
    if (NS > 1) issue(1);
    if (NS > 2) issue(2);

    for (int s = 0; s < NS; s++) {
        if (s + 3 <= NS)
            asm volatile("cp.async.wait_group 2;" ::: "memory");
        else if (s + 2 == NS)
            asm volatile("cp.async.wait_group 1;" ::: "memory");
        else
            asm volatile("cp.async.wait_group 0;" ::: "memory");
        __syncthreads();

        const uint32_t ab = sb + (s % NSTAGE) * BUF_BYTES;
        const uint32_t bb = ab + 10240;

        #pragma unroll
        for (int kk = 0; kk < 2; kk++) {
            const int k0h = kk * 16;
            uint32_t a[4][4];
            #pragma unroll
            for (int mt = 0; mt < 4; mt++)
                ldsm4(a[mt], ab + ((wm + mt * 16 + (t8 & 1) * 8 + lr) * AS_STRIDE
                                   + k0h + (t8 >> 1) * 8) * 2);
            uint32_t b[2][4];
            #pragma unroll
            for (int np = 0; np < 2; np++) {
                if (BNN)
                    ldsm4t(b[np], bb + ((k0h + (t8 & 1) * 8 + lr) * BNN_STRIDE
                                        + wn + np * 16 + (t8 >> 1) * 8) * 2);
                else
                    ldsm4(b[np], bb + ((wn + np * 16 + (t8 >> 1) * 8 + lr) * BNT_STRIDE
                                       + k0h + (t8 & 1) * 8) * 2);
            }
            #pragma unroll
            for (int mt = 0; mt < 4; mt++)
                #pragma unroll
                for (int nt = 0; nt < 4; nt++)
                    asm volatile(
                        "mma.sync.aligned.m16n8k16.row.col.f32.f16.f16.f32 "
                        "{%0,%1,%2,%3}, {%4,%5,%6,%7}, {%8,%9}, {%0,%1,%2,%3};"
                        : "+f"(acc[mt][nt][0]), "+f"(acc[mt][nt][1]),
                          "+f"(acc[mt][nt][2]), "+f"(acc[mt][nt][3])
                        : "r"(a[mt][0]), "r"(a[mt][1]), "r"(a[mt][2]), "r"(a[mt][3]),
                          "r"(b[nt >> 1][(nt & 1) * 2]), "r"(b[nt >> 1][(nt & 1) * 2 + 1]));
        }
        if (s + 3 < NS) issue(s + 3);
    }

    const long nRowsTot = (long)gridDim.x * 128;

    // ---- epilogue
    float rsum[4][2];
    #pragma unroll
    for (int mt = 0; mt < 4; mt++) { rsum[mt][0] = 0.f; rsum[mt][1] = 0.f; }

    #pragma unroll
    for (int mt = 0; mt < 4; mt++) {
        const long row0 = rowBase + wm + mt * 16 + g;
        float sc0 = 1.f, sc1 = 1.f;
        if (EPI == 2) {
            float s0 = 0.f, s1 = 0.f;
            #pragma unroll
            for (int k = 0; k < PSUM_BLKS; k++) {
                s0 += aux[(long)k * nRowsTot + row0];
                s1 += aux[(long)k * nRowsTot + row0 + 8];
            }
            sc0 = 1.f / s0;
            sc1 = 1.f / s1;
        }
        #pragma unroll
        for (int nt = 0; nt < 4; nt++) {
            const long col = colBase + wn + nt * 8 + 2 * c;
            float x0 = acc[mt][nt][0], x1 = acc[mt][nt][1];
            float x2 = acc[mt][nt][2], x3 = acc[mt][nt][3];
            if (EPI == 0) {
                float bx = 0.f, by = 0.f;
                if (bias) { bx = bias[col]; by = bias[col + 1]; }
                x0 += bx; x1 += by; x2 += bx; x3 += by;
            } else if (EPI == 1) {
                x0 = fex2(x0 * escale); x1 = fex2(x1 * escale);
                x2 = fex2(x2 * escale); x3 = fex2(x3 * escale);
                rsum[mt][0] += x0 + x1;
                rsum[mt][1] += x2 + x3;
            } else {
                x0 *= sc0; x1 *= sc0; x2 *= sc1; x3 *= sc1;
                if (resid) {
                    float2 r0 = __half22float2(
                        *reinterpret_cast<const __half2*>(&resid[row0 * rsResid + col]));
                    float2 r1 = __half22float2(
                        *reinterpret_cast<const __half2*>(&resid[(row0 + 8) * rsResid + col]));
                    x0 += r0.x; x1 += r0.y; x2 += r1.x; x3 += r1.y;
                }
            }
            if (sizeof(OutT) == 2) {
                *reinterpret_cast<__half2*>(C + row0 * rsC + col) = __floats2half2_rn(x0, x1);
                *reinterpret_cast<__half2*>(C + (row0 + 8) * rsC + col) = __floats2half2_rn(x2, x3);
            } else {
                *reinterpret_cast<float2*>((float*)C + row0 * rsC + col) = make_float2(x0, x1);
                *reinterpret_cast<float2*>((float*)C + (row0 + 8) * rsC + col) = make_float2(x2, x3);
            }
        }
    }

    if (EPI == 1) {
        float* sred = reinterpret_cast<float*>(dyn);   // [128 rows][4 n-warps]
        __syncthreads();
        #pragma unroll
        for (int mt = 0; mt < 4; mt++) {
            float v0 = rsum[mt][0], v1 = rsum[mt][1];
            v0 += __shfl_xor_sync(0xFFFFFFFFu, v0, 1);
            v0 += __shfl_xor_sync(0xFFFFFFFFu, v0, 2);
            v1 += __shfl_xor_sync(0xFFFFFFFFu, v1, 1);
            v1 += __shfl_xor_sync(0xFFFFFFFFu, v1, 2);
            if (c == 0) {
                const int rl = wm + mt * 16 + g;
                sred[rl * 4 + (wid & 3)] = v0;
                sred[(rl + 8) * 4 + (wid & 3)] = v1;
            }
        }
        __syncthreads();
        if (tid < 128) {
            const float s = sred[tid * 4] + sred[tid * 4 + 1]
                          + sred[tid * 4 + 2] + sred[tid * 4 + 3];
            aux[(long)blockIdx.y * nRowsTot + rowBase + tid] = s;
        }
    }
}

// Generic batched wrapper (no residual).
template <bool BNN, int EPI, typename OutT>
__global__ __launch_bounds__(256, 2) void hgemm(
    const __half* __restrict__ A, const __half* __restrict__ B, OutT* __restrict__ C,
    const float* __restrict__ bias, float* __restrict__ aux, long auxStride,
    float escale, int K,
    long rsA, long bsA, long rsB, long bsB, long rsC, long bsC)
{
    const int bz = blockIdx.z;
    gemm_body<BNN, EPI, OutT>(A + (long)bz * bsA, B + (long)bz * bsB,
                              C + (long)bz * bsC, bias,
                              aux ? aux + (long)bz * auxStride : nullptr,
                              escale, nullptr, 0, K, rsA, rsB, rsC);
}

// Q+K projections in one launch: z = which*NB + b.
__global__ __launch_bounds__(256, 2) void hgemm_projqk(
    const __half* __restrict__ det16, const __half* __restrict__ rel16,
    const __half* __restrict__ wd, const __half* __restrict__ wr,
    const float* __restrict__ bd, const float* __restrict__ br,
    __half* __restrict__ q16, __half* __restrict__ k16)
{
    const int z = blockIdx.z;
    const int which = z >> 3;
    const int b = z & 7;
    const __half* A = which ? rel16 : det16;
    const __half* W = which ? wr : wd;
    const float* bias = which ? br : bd;
    __half* C = which ? k16 : q16;
    gemm_body<false, 0, __half>(A + (long)b * DM, W, C + (long)b * ND * DF,
                                bias, nullptr, 0.f, nullptr, 0,
                                DM, (long)NB * DM, DM, DF);
}

// AV split-K: z = split*NB + b. Split 0 adds the rel16 residual.
__global__ __launch_bounds__(256, 2) void hgemm_av(
    const __half* __restrict__ e16, const __half* __restrict__ v16,
    __half* __restrict__ part, float* __restrict__ psum,
    const __half* __restrict__ rel16)
{
    const int z = blockIdx.z;
    const int split = z >> 3;
    const int b = z & 7;
    const long kOff = (long)split * (ND / KSPLIT);
    gemm_body<true, 2, __half>(
        e16 + (long)b * NR * ND + kOff,
        v16 + (long)b * ND * DF + kOff * DF,
        part + ((long)split * NB + b) * NR * DF,
        nullptr, psum + (long)b * PSUM_BLKS * NR, 0.f,
        split == 0 ? rel16 + (long)b * DM : nullptr, (long)NB * DM,
        ND / KSPLIT, (long)ND, (long)DF, (long)DF);
}

// ---------------------------------------------------------------------------
// One launch converting all five fp32 tensors to fp16.
// ---------------------------------------------------------------------------
__global__ __launch_bounds__(256) void cvt_all(
    const float* __restrict__ det, const float* __restrict__ rel,
    const float* __restrict__ wd, const float* __restrict__ wr,
    const float* __restrict__ wv,
    __half* __restrict__ det16, __half* __restrict__ rel16,
    __half* __restrict__ wd16, __half* __restrict__ wr16, __half* __restrict__ wv16)
{
    const float* src; __half* dst; long n;
    switch (blockIdx.z) {
        case 0: src = det; dst = det16; n = (long)ND * NB * DM; break;
        case 1: src = rel; dst = rel16; n = (long)NR * NB * DM; break;
        case 2: src = wd;  dst = wd16;  n = (long)DF * DM; break;
        case 3: src = wr;  dst = wr16;  n = (long)DF * DM; break;
        default: src = wv; dst = wv16;  n = (long)DF * DM; break;
    }
    long i = ((long)blockIdx.x * blockDim.x + threadIdx.x) * 4;
    const long stride = (long)gridDim.x * blockDim.x * 4;
    for (; i < n; i += stride) {
        float4 v = *reinterpret_cast<const float4*>(src + i);
        __half2* p = reinterpret_cast<__half2*>(dst + i);
        p[0] = __floats2half2_rn(v.x, v.y);
        p[1] = __floats2half2_rn(v.z, v.w);
    }
}

// ---------------------------------------------------------------------------
// out[r][b][:] = LN(part0[b][r][:] + part1[b][r][:]) * gamma + beta
// (residual already folded into part0). 256 threads = 2 rows per block.
// ---------------------------------------------------------------------------
__global__ __launch_bounds__(256) void residual_ln(
    const __half* __restrict__ part,
    const float* __restrict__ gamma, const float* __restrict__ beta,
    float* __restrict__ out)
{
    const int half = threadIdx.x >> 7;
    const int tid = threadIdx.x & 127;
    const long idx = (long)blockIdx.x * 2 + half;   // b*NR + r
    const long b = idx >> 11;
    const long r = idx & 2047;
    const int f = tid * 4;

    const long off1 = (long)NB * NR * DF;
    uint2 a0 = *reinterpret_cast<const uint2*>(&part[idx * DM + f]);
    uint2 a1 = *reinterpret_cast<const uint2*>(&part[off1 + idx * DM + f]);
    const __half2* h0 = reinterpret_cast<const __half2*>(&a0);
    const __half2* h1 = reinterpret_cast<const __half2*>(&a1);
    float2 p00 = __half22float2(h0[0]), p01 = __half22float2(h0[1]);
    float2 p10 = __half22float2(h1[0]), p11 = __half22float2(h1[1]);
    float x0 = p00.x + p10.x, x1 = p00.y + p10.y;
    float x2 = p01.x + p11.x, x3 = p01.y + p11.y;

    float sum = x0 + x1 + x2 + x3;
    float ssq = x0 * x0 + x1 * x1 + x2 * x2 + x3 * x3;
    #pragma unroll
    for (int o = 16; o > 0; o >>= 1) {
        sum += __shfl_xor_sync(0xFFFFFFFFu, sum, o);
        ssq += __shfl_xor_sync(0xFFFFFFFFu, ssq, o);
    }
    __shared__ float s1[2][4], s2[2][4];
    const int w = tid >> 5;
    if ((tid & 31) == 0) { s1[half][w] = sum; s2[half][w] = ssq; }
    __syncthreads();
    sum = s1[half][0] + s1[half][1] + s1[half][2] + s1[half][3];
    ssq = s2[half][0] + s2[half][1] + s2[half][2] + s2[half][3];

    const float mean = sum * (1.f / DM);
    const float var = ssq * (1.f / DM) - mean * mean;
    const float rstd = rsqrtf(var + 1e-5f);

    const float4 g4 = *reinterpret_cast<const float4*>(&gamma[f]);
    const float4 be4 = *reinterpret_cast<const float4*>(&beta[f]);
    float4 o4;
    o4.x = (x0 - mean) * rstd * g4.x + be4.x;
    o4.y = (x1 - mean) * rstd * g4.y + be4.y;
    o4.z = (x2 - mean) * rstd * g4.z + be4.z;
    o4.w = (x3 - mean) * rstd * g4.w + be4.w;
    *reinterpret_cast<float4*>(&out[(r * NB + b) * DM + f]) = o4;
}

// ---------------------------------------------------------------------------
extern "C" void kernel_launch(void* const* d_in, const int* in_sizes, int n_in,
                              void* d_out, int out_size)
{
    const float* det_in = (const float*)d_in[0];
    const float* rel_in = (const float*)d_in[1];
    const float* W_det  = (const float*)d_in[2];
    const float* b_det  = (const float*)d_in[3];
    const float* W_rel  = (const float*)d_in[4];
    const float* b_rel  = (const float*)d_in[5];
    const float* W_val  = (const float*)d_in[6];
    const float* b_val  = (const float*)d_in[7];
    const float* gamma  = (const float*)d_in[8];
    const float* beta   = (const float*)d_in[9];
    float* out = (float*)d_out;

    __half *det16, *rel16, *wd16, *wr16, *wv16, *q16, *k16, *v16, *s16, *part;
    float *psum;
    cudaGetSymbolAddress((void**)&det16, g_det16);
    cudaGetSymbolAddress((void**)&rel16, g_rel16);
    cudaGetSymbolAddress((void**)&wd16, g_wd16);
    cudaGetSymbolAddress((void**)&wr16, g_wr16);
    cudaGetSymbolAddress((void**)&wv16, g_wv16);
    cudaGetSymbolAddress((void**)&q16, g_q16);
    cudaGetSymbolAddress((void**)&k16, g_k16);
    cudaGetSymbolAddress((void**)&v16, g_v16);
    cudaGetSymbolAddress((void**)&s16, g_s16);
    cudaGetSymbolAddress((void**)&part, g_part);
    cudaGetSymbolAddress((void**)&psum, g_psum);

    cudaFuncSetAttribute(hgemm_projqk, cudaFuncAttributeMaxDynamicSharedMemorySize, SMEM_BYTES);
    cudaFuncSetAttribute(hgemm<false, 0, __half>, cudaFuncAttributeMaxDynamicSharedMemorySize, SMEM_BYTES);
    cudaFuncSetAttribute(hgemm<false, 1, __half>, cudaFuncAttributeMaxDynamicSharedMemorySize, SMEM_BYTES);
    cudaFuncSetAttribute(hgemm_av, cudaFuncAttributeMaxDynamicSharedMemorySize, SMEM_BYTES);

    // Side stream + events (created once, outside capture).
    static cudaStream_t s2 = nullptr;
    static cudaEvent_t evCvt = nullptr, evV = nullptr;
    if (!s2) {
        cudaStreamCreateWithFlags(&s2, cudaStreamNonBlocking);
        cudaEventCreateWithFlags(&evCvt, cudaEventDisableTiming);
        cudaEventCreateWithFlags(&evV, cudaEventDisableTiming);
    }

    dim3 blk(256);

    // --- all fp32->fp16 conversions in ONE launch
    cvt_all<<<dim3(2048, 1, 5), blk>>>(det_in, rel_in, W_det, W_rel, W_val,
                                       det16, rel16, wd16, wr16, wv16);
    cudaEventRecord(evCvt, 0);

    // --- side stream: pass-through copy + V projection
    cudaStreamWaitEvent(s2, evCvt, 0);
    cudaMemcpyAsync(out, det_in, (size_t)ND * NB * DM * sizeof(float),
                    cudaMemcpyDeviceToDevice, s2);
    dim3 gv(ND / 128, DF / 128, NB);
    hgemm<false, 0, __half><<<gv, blk, SMEM_BYTES, s2>>>(
        det16, wv16, v16, b_val, nullptr, 0L, 0.f, DM,
        (long)NB * DM, (long)DM, (long)DM, 0L, (long)DF, (long)ND * DF);
    cudaEventRecord(evV, s2);

    // --- main stream: Q+K projections (one launch, 2048 CTAs)
    dim3 gqk(ND / 128, DF / 128, 2 * NB);
    hgemm_projqk<<<gqk, blk, SMEM_BYTES>>>(det16, rel16, wd16, wr16,
                                           b_det, b_rel, q16, k16);

    // --- scores (NT) with fused exp + partial row sums (2048 CTAs)
    const float scl2 = (1.f / sqrtf((float)DF)) * 1.44269504f;  // log2(e)/sqrt(F)
    dim3 gs(NR / 128, ND / 128, NB);
    hgemm<false, 1, __half><<<gs, blk, SMEM_BYTES>>>(
        k16, q16, s16, nullptr, psum, (long)PSUM_BLKS * NR, scl2, DF,
        (long)DF, (long)NR * DF, (long)DF, (long)ND * DF, (long)ND, (long)NR * ND);

    // --- join: AV needs v16 from the side stream
    cudaStreamWaitEvent(0, evV, 0);

    // --- AV split-K=2 (1024 CTAs); split 0 adds rel16 residual
    dim3 ga(NR / 128, DF / 128, KSPLIT * NB);
    hgemm_av<<<ga, blk, SMEM_BYTES>>>(s16, v16, part, psum, rel16);

    // --- LayerNorm over summed partials -> out[Nd*B*D + ...]
    residual_ln<<<NB * NR / 2, 256>>>(part, gamma, beta,
                                      out + (size_t)ND * NB * DM);
}